// round 1
// baseline (speedup 1.0000x reference)
#include <cuda_runtime.h>

#define NBINS 256

__device__ int   g_hist_src[NBINS];
__device__ int   g_hist_tgt[NBINS];
__device__ float g_pxmap[NBINS];
__device__ float g_fs[NBINS];

// ---------------------------------------------------------------------------
// Kernel 0: zero histograms, build floating_space (np.arange semantics: f64
// i*step, cast to f32, clipped to [0,1]).
// ---------------------------------------------------------------------------
__global__ void k_init() {
    int t = threadIdx.x;
    g_hist_src[t] = 0;
    g_hist_tgt[t] = 0;
    double step = 1.0 / 255.0;
    float v = (float)((double)t * step);
    v = fminf(fmaxf(v, 0.0f), 1.0f);
    g_fs[t] = v;
}

// ---------------------------------------------------------------------------
// Kernel 1: rescale, histogram src channel-0 and tgt luma. Writes the rescaled
// source value into xbuf (= d_out used as scratch) so pass 3 reads 4MB instead
// of re-touching 12MB of strided src lines.
// blockDim.x MUST be 256.
// ---------------------------------------------------------------------------
__global__ void k_hist(const float* __restrict__ src,
                       const float* __restrict__ tgt,
                       float* __restrict__ xbuf, int n) {
    __shared__ int sh_src[NBINS];
    __shared__ int sh_tgt[NBINS];
    int t = threadIdx.x;
    sh_src[t] = 0;
    sh_tgt[t] = 0;
    __syncthreads();

    const float SC = 127.0f / 255.0f;
    int stride = gridDim.x * blockDim.x;
    for (int i = blockIdx.x * blockDim.x + t; i < n; i += stride) {
        // src channel 0
        float r = src[3 * i];
        float x = (r + 1.0f) * SC;
        xbuf[i] = x;
        int b = (int)(x * 256.0f);
        b = min(max(b, 0), NBINS - 1);
        atomicAdd(&sh_src[b], 1);

        // tgt luma
        float tr = (tgt[3 * i + 0] + 1.0f) * SC;
        float tg = (tgt[3 * i + 1] + 1.0f) * SC;
        float tb = (tgt[3 * i + 2] + 1.0f) * SC;
        float y = tr * 0.299f + tg * 0.587f + tb * 0.114f;
        int b2 = (int)(y * 256.0f);
        b2 = min(max(b2, 0), NBINS - 1);
        atomicAdd(&sh_tgt[b2], 1);
    }
    __syncthreads();
    if (sh_src[t]) atomicAdd(&g_hist_src[t], sh_src[t]);
    if (sh_tgt[t]) atomicAdd(&g_hist_tgt[t], sh_tgt[t]);
}

// ---------------------------------------------------------------------------
// Kernel 2 (1 block, 256 threads): cumsum both hists, normalize to CDFs,
// then pxmap = interpolate(dx=cdftgt, dy=floating_space, x=cdfsrc) with the
// exact argmax-of-sign semantics of the reference.
// ---------------------------------------------------------------------------
__global__ void k_cdf_pxmap(int n) {
    __shared__ int   a[NBINS], b[NBINS];
    __shared__ float cdfsrc[NBINS], cdftgt[NBINS], fsv[NBINS];
    int t = threadIdx.x;
    a[t] = g_hist_src[t];
    b[t] = g_hist_tgt[t];
    fsv[t] = g_fs[t];
    __syncthreads();

    // Hillis-Steele inclusive scan
    #pragma unroll
    for (int off = 1; off < NBINS; off <<= 1) {
        int av = a[t], bv = b[t];
        int a2 = (t >= off) ? a[t - off] : 0;
        int b2 = (t >= off) ? b[t - off] : 0;
        __syncthreads();
        a[t] = av + a2;
        b[t] = bv + b2;
        __syncthreads();
    }

    // cdf_min = cdf[0] (cumsum of non-negative counts is non-decreasing)
    int mins = a[0];
    int mint = b[0];
    float den = (float)(n - 1);
    cdfsrc[t] = (float)(a[t] - mins) / den;
    cdftgt[t] = (float)(b[t] - mint) / den;
    __syncthreads();

    // interpolate(dx=cdftgt, dy=fs, x=cdfsrc[t])
    float x = cdfsrc[t];
    int first_gt = -1, first_eq = -1;
    for (int j = 0; j < NBINS; j++) {
        float d = cdftgt[j];
        if (first_gt < 0 && d > x)  first_gt = j;
        if (first_eq < 0 && d == x) first_eq = j;
    }
    int ind1 = (first_gt >= 0) ? first_gt : ((first_eq >= 0) ? first_eq : 0);
    int ind0 = max(ind1 - 1, 0);

    float dx0 = cdftgt[ind0], dx1 = cdftgt[ind1];
    float dy0 = fsv[ind0],    dy1 = fsv[ind1];
    float denom = dx1 - dx0;
    float sd = (denom == 0.0f) ? 1.0f : denom;
    float interp = dy0 + (dy1 - dy0) * (x - dx0) / sd;

    float res = (x <= cdftgt[0]) ? fsv[0]
              : ((x >= cdftgt[NBINS - 1]) ? fsv[NBINS - 1] : interp);
    g_pxmap[t] = res;
}

// ---------------------------------------------------------------------------
// Kernel 3: per-pixel interpolate(dx=floating_space, dy=pxmap, x=source),
// clip, rescale back. In-place on d_out (xbuf from kernel 1).
// blockDim.x MUST be 256.
// ---------------------------------------------------------------------------
__global__ void k_apply(float* __restrict__ io, int n) {
    __shared__ float fsv[NBINS];
    __shared__ float pm[NBINS];
    int t = threadIdx.x;
    fsv[t] = g_fs[t];
    pm[t]  = g_pxmap[t];
    __syncthreads();

    float fs_last = fsv[NBINS - 1];
    int stride = gridDim.x * blockDim.x;
    for (int i = blockIdx.x * blockDim.x + t; i < n; i += stride) {
        float x = io[i];
        float res;
        if (x <= fsv[0]) {
            res = pm[0];
        } else if (x >= fs_last) {
            res = pm[NBINS - 1];
        } else {
            // first j with fsv[j] > x  (fs strictly increasing, x < fs[255])
            int j = (int)(x * 255.0f) + 1;
            j = min(max(j, 1), NBINS - 1);
            while (j > 1 && fsv[j - 1] > x) --j;
            while (j < NBINS - 1 && fsv[j] <= x) ++j;
            int j0 = j - 1;
            float dx0 = fsv[j0], dx1 = fsv[j];
            float denom = dx1 - dx0;
            float sd = (denom == 0.0f) ? 1.0f : denom;
            res = pm[j0] + (pm[j] - pm[j0]) * (x - dx0) / sd;
        }
        res = fminf(fmaxf(res, 0.0f), 1.0f);
        io[i] = res * (255.0f / 127.0f) - 1.0f;
    }
}

// ---------------------------------------------------------------------------
extern "C" void kernel_launch(void* const* d_in, const int* in_sizes, int n_in,
                              void* d_out, int out_size) {
    const float* src = (const float*)d_in[0];
    const float* tgt = (const float*)d_in[1];
    float* out = (float*)d_out;
    int n = in_sizes[0] / 3;  // H*W pixels

    int blocks = (n + 255) / 256;
    if (blocks > 8192) blocks = 8192;

    k_init<<<1, 256>>>();
    k_hist<<<blocks, 256>>>(src, tgt, out, n);
    k_cdf_pxmap<<<1, 256>>>(n);
    k_apply<<<blocks, 256>>>(out, n);
}

// round 2
// speedup vs baseline: 2.3989x; 2.3989x over previous
#include <cuda_runtime.h>

#define NBINS 256

__device__ int   g_hist[2 * NBINS];   // [0..255]=src, [256..511]=tgt
__device__ float g_pxmap[NBINS];
__device__ float g_fs[NBINS];

// ---------------------------------------------------------------------------
// Kernel 0: zero histograms, build floating_space (np.arange semantics).
// ---------------------------------------------------------------------------
__global__ void k_init() {
    int t = threadIdx.x;
    g_hist[t] = 0;
    g_hist[t + NBINS] = 0;
    double step = 1.0 / 255.0;
    float v = (float)((double)t * step);
    v = fminf(fmaxf(v, 0.0f), 1.0f);
    g_fs[t] = v;
}

// ---------------------------------------------------------------------------
// Kernel 1: rescale + histogram src channel-0 and tgt luma, float4 path.
// Writes rescaled source x into xbuf (d_out as scratch).
// blockDim.x MUST be 256.
// ---------------------------------------------------------------------------
__global__ void k_hist(const float* __restrict__ src,
                       const float* __restrict__ tgt,
                       float* __restrict__ xbuf, int n) {
    __shared__ int sh[2 * NBINS];
    int t = threadIdx.x;
    sh[t] = 0;
    sh[t + NBINS] = 0;
    __syncthreads();

    const float SC = 127.0f / 255.0f;
    const float4* s4 = (const float4*)src;
    const float4* t4 = (const float4*)tgt;
    float4* x4 = (float4*)xbuf;

    int nq = n >> 2;
    int stride = gridDim.x * blockDim.x;

    for (int q = blockIdx.x * blockDim.x + t; q < nq; q += stride) {
        // 4 pixels = 12 floats = 3 float4s
        float4 a = s4[3 * q + 0];
        float4 b = s4[3 * q + 1];
        float4 c = s4[3 * q + 2];
        // R channels at float offsets 0,3,6,9 -> a.x, a.w, b.z, c.y
        float x0 = (a.x + 1.0f) * SC;
        float x1 = (a.w + 1.0f) * SC;
        float x2 = (b.z + 1.0f) * SC;
        float x3 = (c.y + 1.0f) * SC;
        x4[q] = make_float4(x0, x1, x2, x3);
        int b0 = min(max((int)(x0 * 256.0f), 0), NBINS - 1);
        int b1 = min(max((int)(x1 * 256.0f), 0), NBINS - 1);
        int b2 = min(max((int)(x2 * 256.0f), 0), NBINS - 1);
        int b3 = min(max((int)(x3 * 256.0f), 0), NBINS - 1);
        atomicAdd(&sh[b0], 1);
        atomicAdd(&sh[b1], 1);
        atomicAdd(&sh[b2], 1);
        atomicAdd(&sh[b3], 1);

        float4 ta = t4[3 * q + 0];
        float4 tb = t4[3 * q + 1];
        float4 tc = t4[3 * q + 2];
        // pixel i: (R,G,B); y = 0.299R+0.587G+0.114B, applied to rescaled vals.
        // Rescale is affine & same for all channels: y_resc = (y_raw+1)*SC since
        // coefficients sum to 1.0 -- but match reference exactly: rescale first.
        float r0 = (ta.x + 1.0f) * SC, g0 = (ta.y + 1.0f) * SC, bl0 = (ta.z + 1.0f) * SC;
        float r1 = (ta.w + 1.0f) * SC, g1 = (tb.x + 1.0f) * SC, bl1 = (tb.y + 1.0f) * SC;
        float r2 = (tb.z + 1.0f) * SC, g2 = (tb.w + 1.0f) * SC, bl2 = (tc.x + 1.0f) * SC;
        float r3 = (tc.y + 1.0f) * SC, g3 = (tc.z + 1.0f) * SC, bl3 = (tc.w + 1.0f) * SC;
        float y0 = r0 * 0.299f + g0 * 0.587f + bl0 * 0.114f;
        float y1 = r1 * 0.299f + g1 * 0.587f + bl1 * 0.114f;
        float y2 = r2 * 0.299f + g2 * 0.587f + bl2 * 0.114f;
        float y3 = r3 * 0.299f + g3 * 0.587f + bl3 * 0.114f;
        int c0 = min(max((int)(y0 * 256.0f), 0), NBINS - 1);
        int c1 = min(max((int)(y1 * 256.0f), 0), NBINS - 1);
        int c2 = min(max((int)(y2 * 256.0f), 0), NBINS - 1);
        int c3 = min(max((int)(y3 * 256.0f), 0), NBINS - 1);
        atomicAdd(&sh[NBINS + c0], 1);
        atomicAdd(&sh[NBINS + c1], 1);
        atomicAdd(&sh[NBINS + c2], 1);
        atomicAdd(&sh[NBINS + c3], 1);
    }

    // scalar tail (n not divisible by 4)
    for (int i = 4 * nq + blockIdx.x * blockDim.x + t; i < n; i += stride) {
        float x = (src[3 * i] + 1.0f) * SC;
        xbuf[i] = x;
        int bi = min(max((int)(x * 256.0f), 0), NBINS - 1);
        atomicAdd(&sh[bi], 1);
        float tr = (tgt[3 * i + 0] + 1.0f) * SC;
        float tg = (tgt[3 * i + 1] + 1.0f) * SC;
        float tbv = (tgt[3 * i + 2] + 1.0f) * SC;
        float y = tr * 0.299f + tg * 0.587f + tbv * 0.114f;
        int ci = min(max((int)(y * 256.0f), 0), NBINS - 1);
        atomicAdd(&sh[NBINS + ci], 1);
    }

    __syncthreads();
    int v0 = sh[t], v1 = sh[t + NBINS];
    if (v0) atomicAdd(&g_hist[t], v0);
    if (v1) atomicAdd(&g_hist[t + NBINS], v1);
}

// ---------------------------------------------------------------------------
// Kernel 2 (1 block, 256 threads): scan -> CDFs -> pxmap via the exact
// argmax-of-sign interpolate semantics.
// ---------------------------------------------------------------------------
__global__ void k_cdf_pxmap(int n) {
    __shared__ int   a[NBINS], b[NBINS];
    __shared__ float cdftgt[NBINS], fsv[NBINS];
    int t = threadIdx.x;
    a[t] = g_hist[t];
    b[t] = g_hist[t + NBINS];
    fsv[t] = g_fs[t];
    __syncthreads();

    #pragma unroll
    for (int off = 1; off < NBINS; off <<= 1) {
        int av = a[t], bv = b[t];
        int a2 = (t >= off) ? a[t - off] : 0;
        int b2 = (t >= off) ? b[t - off] : 0;
        __syncthreads();
        a[t] = av + a2;
        b[t] = bv + b2;
        __syncthreads();
    }

    int mins = a[0];
    int mint = b[0];
    float den = (float)(n - 1);
    float x = (float)(a[t] - mins) / den;       // cdfsrc[t]
    cdftgt[t] = (float)(b[t] - mint) / den;
    __syncthreads();

    int first_gt = -1, first_eq = -1;
    #pragma unroll 8
    for (int j = 0; j < NBINS; j++) {
        float d = cdftgt[j];
        if (first_gt < 0 && d > x)  first_gt = j;
        if (first_eq < 0 && d == x) first_eq = j;
    }
    int ind1 = (first_gt >= 0) ? first_gt : ((first_eq >= 0) ? first_eq : 0);
    int ind0 = max(ind1 - 1, 0);

    float dx0 = cdftgt[ind0], dx1 = cdftgt[ind1];
    float dy0 = fsv[ind0],    dy1 = fsv[ind1];
    float denom = dx1 - dx0;
    float sd = (denom == 0.0f) ? 1.0f : denom;
    float interp = dy0 + (dy1 - dy0) * (x - dx0) / sd;

    float res = (x <= cdftgt[0]) ? fsv[0]
              : ((x >= cdftgt[NBINS - 1]) ? fsv[NBINS - 1] : interp);
    g_pxmap[t] = res;
}

// ---------------------------------------------------------------------------
// Kernel 3: per-pixel interpolate on the fixed fs grid, clip, rescale back.
// float4 in-place on d_out. blockDim.x MUST be 256.
// ---------------------------------------------------------------------------
__device__ __forceinline__ float apply_one(float x, const float* fsv, const float* pm) {
    float res;
    if (x <= fsv[0]) {
        res = pm[0];
    } else if (x >= fsv[NBINS - 1]) {
        res = pm[NBINS - 1];
    } else {
        int j = (int)(x * 255.0f) + 1;
        j = min(max(j, 1), NBINS - 1);
        while (j > 1 && fsv[j - 1] > x) --j;
        while (j < NBINS - 1 && fsv[j] <= x) ++j;
        int j0 = j - 1;
        float dx0 = fsv[j0], dx1 = fsv[j];
        float denom = dx1 - dx0;
        float sd = (denom == 0.0f) ? 1.0f : denom;
        res = pm[j0] + (pm[j] - pm[j0]) * (x - dx0) / sd;
    }
    res = fminf(fmaxf(res, 0.0f), 1.0f);
    return res * (255.0f / 127.0f) - 1.0f;
}

__global__ void k_apply(float* __restrict__ io, int n) {
    __shared__ float fsv[NBINS];
    __shared__ float pm[NBINS];
    int t = threadIdx.x;
    fsv[t] = g_fs[t];
    pm[t]  = g_pxmap[t];
    __syncthreads();

    float4* io4 = (float4*)io;
    int nq = n >> 2;
    int stride = gridDim.x * blockDim.x;

    for (int q = blockIdx.x * blockDim.x + t; q < nq; q += stride) {
        float4 v = io4[q];
        v.x = apply_one(v.x, fsv, pm);
        v.y = apply_one(v.y, fsv, pm);
        v.z = apply_one(v.z, fsv, pm);
        v.w = apply_one(v.w, fsv, pm);
        io4[q] = v;
    }
    for (int i = 4 * nq + blockIdx.x * blockDim.x + t; i < n; i += stride) {
        io[i] = apply_one(io[i], fsv, pm);
    }
}

// ---------------------------------------------------------------------------
extern "C" void kernel_launch(void* const* d_in, const int* in_sizes, int n_in,
                              void* d_out, int out_size) {
    const float* src = (const float*)d_in[0];
    const float* tgt = (const float*)d_in[1];
    float* out = (float*)d_out;
    int n = in_sizes[0] / 3;  // H*W pixels
    int nq = n >> 2;

    int hist_blocks = (nq + 255) / 256;
    if (hist_blocks > 592) hist_blocks = 592;   // ~4 CTAs/SM worth of looping work
    if (hist_blocks < 1) hist_blocks = 1;

    int apply_blocks = (nq + 255) / 256;
    if (apply_blocks > 2048) apply_blocks = 2048;
    if (apply_blocks < 1) apply_blocks = 1;

    k_init<<<1, 256>>>();
    k_hist<<<hist_blocks, 256>>>(src, tgt, out, n);
    k_cdf_pxmap<<<1, 256>>>(n);
    k_apply<<<apply_blocks, 256>>>(out, n);
}

// round 3
// speedup vs baseline: 2.6305x; 1.0965x over previous
#include <cuda_runtime.h>

#define NBINS 256
#define TPB   256
#define KQ    2      // quads held in registers per thread

__device__ int   g_hist[2 * NBINS];          // zero-init; restored to zero each run
__device__ float g_pxmap[NBINS];
__device__ int   g_done0;
__device__ int   g_done1;
__device__ volatile int g_release;

// Branchless per-pixel interpolate on the fixed fs grid + clip + rescale-back.
__device__ __forceinline__ float apply1(float x,
                                        const float* __restrict__ fsv,
                                        const float* __restrict__ As,
                                        const float* __restrict__ Bs,
                                        float pm0, float pm255,
                                        float fs0, float fs255) {
    int j = (int)(x * 255.0f) + 1;
    j = min(max(j, 1), NBINS - 1);
    if (fsv[j - 1] > x) --j;          // guess can be off by at most 1
    j = max(j, 1);
    if (fsv[j] <= x) ++j;
    j = min(j, NBINS - 1);
    float r = fmaf(As[j], x, Bs[j]);
    if (x <= fs0)   r = pm0;
    if (x >= fs255) r = pm255;
    r = fminf(fmaxf(r, 0.0f), 1.0f);
    return fmaf(r, 255.0f / 127.0f, -1.0f);
}

__global__ void __launch_bounds__(TPB, 4) k_fused(const float* __restrict__ src,
                                                  const float* __restrict__ tgt,
                                                  float* __restrict__ out, int n) {
    __shared__ int   sh[2 * NBINS];
    __shared__ float fsv[NBINS], pmS[NBINS], As[NBINS], Bs[NBINS];
    __shared__ int   is_last;

    const int t    = threadIdx.x;
    const int nth  = gridDim.x * TPB;
    const int gtid = blockIdx.x * TPB + t;
    const int nq   = n >> 2;
    const float SC = 127.0f / 255.0f;

    sh[t] = 0;
    sh[t + NBINS] = 0;
    {   // floating_space: np.arange semantics (f64 i*step -> f32), clipped
        float v = (float)((double)t * (1.0 / 255.0));
        fsv[t] = fminf(fmaxf(v, 0.0f), 1.0f);
    }
    __syncthreads();

    const float4* s4 = (const float4*)src;
    const float4* t4 = (const float4*)tgt;
    float4*       o4 = (float4*)out;

    // ---------------- Phase 1: rescale + histograms ----------------
    float xr[4 * KQ];

    #pragma unroll
    for (int k = 0; k < KQ; ++k) {
        int q = gtid + k * nth;
        if (q < nq) {
            float4 a = s4[3 * q + 0];
            float4 b = s4[3 * q + 1];
            float4 c = s4[3 * q + 2];
            float x0 = (a.x + 1.0f) * SC, x1 = (a.w + 1.0f) * SC;
            float x2 = (b.z + 1.0f) * SC, x3 = (c.y + 1.0f) * SC;
            xr[4 * k + 0] = x0; xr[4 * k + 1] = x1;
            xr[4 * k + 2] = x2; xr[4 * k + 3] = x3;
            atomicAdd(&sh[min(max((int)(x0 * 256.0f), 0), NBINS - 1)], 1);
            atomicAdd(&sh[min(max((int)(x1 * 256.0f), 0), NBINS - 1)], 1);
            atomicAdd(&sh[min(max((int)(x2 * 256.0f), 0), NBINS - 1)], 1);
            atomicAdd(&sh[min(max((int)(x3 * 256.0f), 0), NBINS - 1)], 1);

            float4 ta = t4[3 * q + 0];
            float4 tb = t4[3 * q + 1];
            float4 tc = t4[3 * q + 2];
            float y0 = (ta.x + 1.0f) * SC * 0.299f + (ta.y + 1.0f) * SC * 0.587f + (ta.z + 1.0f) * SC * 0.114f;
            float y1 = (ta.w + 1.0f) * SC * 0.299f + (tb.x + 1.0f) * SC * 0.587f + (tb.y + 1.0f) * SC * 0.114f;
            float y2 = (tb.z + 1.0f) * SC * 0.299f + (tb.w + 1.0f) * SC * 0.587f + (tc.x + 1.0f) * SC * 0.114f;
            float y3 = (tc.y + 1.0f) * SC * 0.299f + (tc.z + 1.0f) * SC * 0.587f + (tc.w + 1.0f) * SC * 0.114f;
            atomicAdd(&sh[NBINS + min(max((int)(y0 * 256.0f), 0), NBINS - 1)], 1);
            atomicAdd(&sh[NBINS + min(max((int)(y1 * 256.0f), 0), NBINS - 1)], 1);
            atomicAdd(&sh[NBINS + min(max((int)(y2 * 256.0f), 0), NBINS - 1)], 1);
            atomicAdd(&sh[NBINS + min(max((int)(y3 * 256.0f), 0), NBINS - 1)], 1);
        }
    }
    // Overflow quads (shape bigger than register capacity): spill x to out.
    for (int q = gtid + KQ * nth; q < nq; q += nth) {
        float4 a = s4[3 * q + 0];
        float4 b = s4[3 * q + 1];
        float4 c = s4[3 * q + 2];
        float x0 = (a.x + 1.0f) * SC, x1 = (a.w + 1.0f) * SC;
        float x2 = (b.z + 1.0f) * SC, x3 = (c.y + 1.0f) * SC;
        o4[q] = make_float4(x0, x1, x2, x3);
        atomicAdd(&sh[min(max((int)(x0 * 256.0f), 0), NBINS - 1)], 1);
        atomicAdd(&sh[min(max((int)(x1 * 256.0f), 0), NBINS - 1)], 1);
        atomicAdd(&sh[min(max((int)(x2 * 256.0f), 0), NBINS - 1)], 1);
        atomicAdd(&sh[min(max((int)(x3 * 256.0f), 0), NBINS - 1)], 1);
        float4 ta = t4[3 * q + 0];
        float4 tb = t4[3 * q + 1];
        float4 tc = t4[3 * q + 2];
        float y0 = (ta.x + 1.0f) * SC * 0.299f + (ta.y + 1.0f) * SC * 0.587f + (ta.z + 1.0f) * SC * 0.114f;
        float y1 = (ta.w + 1.0f) * SC * 0.299f + (tb.x + 1.0f) * SC * 0.587f + (tb.y + 1.0f) * SC * 0.114f;
        float y2 = (tb.z + 1.0f) * SC * 0.299f + (tb.w + 1.0f) * SC * 0.587f + (tc.x + 1.0f) * SC * 0.114f;
        float y3 = (tc.y + 1.0f) * SC * 0.299f + (tc.z + 1.0f) * SC * 0.587f + (tc.w + 1.0f) * SC * 0.114f;
        atomicAdd(&sh[NBINS + min(max((int)(y0 * 256.0f), 0), NBINS - 1)], 1);
        atomicAdd(&sh[NBINS + min(max((int)(y1 * 256.0f), 0), NBINS - 1)], 1);
        atomicAdd(&sh[NBINS + min(max((int)(y2 * 256.0f), 0), NBINS - 1)], 1);
        atomicAdd(&sh[NBINS + min(max((int)(y3 * 256.0f), 0), NBINS - 1)], 1);
    }
    // Tail scalar pixels (n % 4): at most 3, one per thread, kept in register.
    float xtail = 0.0f;
    const int tidx = 4 * nq + gtid;
    if (tidx < n) {
        xtail = (src[3 * tidx] + 1.0f) * SC;
        atomicAdd(&sh[min(max((int)(xtail * 256.0f), 0), NBINS - 1)], 1);
        float yr = (tgt[3 * tidx + 0] + 1.0f) * SC;
        float yg = (tgt[3 * tidx + 1] + 1.0f) * SC;
        float yb = (tgt[3 * tidx + 2] + 1.0f) * SC;
        float y  = yr * 0.299f + yg * 0.587f + yb * 0.114f;
        atomicAdd(&sh[NBINS + min(max((int)(y * 256.0f), 0), NBINS - 1)], 1);
    }

    __syncthreads();
    {
        int v0 = sh[t];         if (v0) atomicAdd(&g_hist[t], v0);
        int v1 = sh[t + NBINS]; if (v1) atomicAdd(&g_hist[t + NBINS], v1);
    }

    // ---------------- Device-wide barrier ----------------
    if (t == 0) {
        __threadfence();
        int old = atomicAdd(&g_done0, 1);
        is_last = (old == (int)gridDim.x - 1);
    }
    __syncthreads();

    if (is_last) {
        // ---- CDF + pxmap (this block only) ----
        __threadfence();
        int av = *(volatile int*)&g_hist[t];
        int bv = *(volatile int*)&g_hist[t + NBINS];
        __syncthreads();
        sh[t] = av;
        sh[t + NBINS] = bv;
        __syncthreads();
        #pragma unroll
        for (int off = 1; off < NBINS; off <<= 1) {
            int aself = sh[t], bself = sh[t + NBINS];
            int aprev = (t >= off) ? sh[t - off] : 0;
            int bprev = (t >= off) ? sh[t + NBINS - off] : 0;
            __syncthreads();
            sh[t] = aself + aprev;
            sh[t + NBINS] = bself + bprev;
            __syncthreads();
        }
        int mins = sh[0], mint = sh[NBINS];     // cdf_min = cdf[0]
        float den = (float)(n - 1);
        float x  = (float)(sh[t] - mins) / den;             // cdfsrc[t]
        float ct = (float)(sh[t + NBINS] - mint) / den;     // cdftgt[t]
        As[t] = ct;                                         // temp: cdftgt
        __syncthreads();

        // upper_bound: first j with cdftgt[j] > x (sorted); edges overridden below
        int lo = 0, hi = NBINS - 1;
        while (lo < hi) { int mid = (lo + hi) >> 1; if (As[mid] > x) hi = mid; else lo = mid + 1; }
        int ind1 = lo;
        int ind0 = max(ind1 - 1, 0);
        float dx0 = As[ind0], dx1 = As[ind1];
        float dy0 = fsv[ind0], dy1 = fsv[ind1];
        float dnm = dx1 - dx0;
        float sd  = (dnm == 0.0f) ? 1.0f : dnm;
        float interp = dy0 + (dy1 - dy0) * (x - dx0) / sd;
        float res = (x <= As[0]) ? fsv[0]
                  : ((x >= As[NBINS - 1]) ? fsv[NBINS - 1] : interp);
        pmS[t] = res;
        g_pxmap[t] = res;
        __threadfence();
        __syncthreads();
        if (t == 0) g_release = 1;
    } else {
        if (t == 0) {
            while (g_release == 0) __nanosleep(32);
            __threadfence();   // acquire
        }
        __syncthreads();
        pmS[t] = __ldcg(&g_pxmap[t]);
    }
    __syncthreads();

    // ---- slope/intercept tables (every block, in its own shared) ----
    if (t > 0) {
        float d = fsv[t] - fsv[t - 1];          // strictly > 0
        float a = (pmS[t] - pmS[t - 1]) / d;
        As[t] = a;
        Bs[t] = pmS[t - 1] - a * fsv[t - 1];
    }
    __syncthreads();

    // ---------------- Phase 3: apply ----------------
    const float pm0 = pmS[0], pm255 = pmS[NBINS - 1];
    const float fs0 = fsv[0], fs255 = fsv[NBINS - 1];

    #pragma unroll
    for (int k = 0; k < KQ; ++k) {
        int q = gtid + k * nth;
        if (q < nq) {
            float4 v;
            v.x = apply1(xr[4 * k + 0], fsv, As, Bs, pm0, pm255, fs0, fs255);
            v.y = apply1(xr[4 * k + 1], fsv, As, Bs, pm0, pm255, fs0, fs255);
            v.z = apply1(xr[4 * k + 2], fsv, As, Bs, pm0, pm255, fs0, fs255);
            v.w = apply1(xr[4 * k + 3], fsv, As, Bs, pm0, pm255, fs0, fs255);
            o4[q] = v;
        }
    }
    for (int q = gtid + KQ * nth; q < nq; q += nth) {
        float4 v = o4[q];   // spilled x values
        v.x = apply1(v.x, fsv, As, Bs, pm0, pm255, fs0, fs255);
        v.y = apply1(v.y, fsv, As, Bs, pm0, pm255, fs0, fs255);
        v.z = apply1(v.z, fsv, As, Bs, pm0, pm255, fs0, fs255);
        v.w = apply1(v.w, fsv, As, Bs, pm0, pm255, fs0, fs255);
        o4[q] = v;
    }
    if (tidx < n) out[tidx] = apply1(xtail, fsv, As, Bs, pm0, pm255, fs0, fs255);

    // ---------------- Cleanup: restore globals to zero for next replay ----------------
    __syncthreads();
    if (t == 0) {
        __threadfence();
        int old = atomicAdd(&g_done1, 1);
        if (old == (int)gridDim.x - 1) {
            #pragma unroll 8
            for (int i = 0; i < 2 * NBINS; ++i) g_hist[i] = 0;
            g_done0 = 0;
            g_done1 = 0;
            __threadfence();
            g_release = 0;
        }
    }
}

extern "C" void kernel_launch(void* const* d_in, const int* in_sizes, int n_in,
                              void* d_out, int out_size) {
    const float* src = (const float*)d_in[0];
    const float* tgt = (const float*)d_in[1];
    float* out = (float*)d_out;
    int n = in_sizes[0] / 3;   // H*W pixels
    int nq = n >> 2;

    int blocks = (nq + TPB * KQ - 1) / (TPB * KQ);
    if (blocks < 1) blocks = 1;
    if (blocks > 592) blocks = 592;   // co-residency cap: 4 CTAs/SM x 148 SMs

    k_fused<<<blocks, TPB>>>(src, tgt, out, n);
}